// round 3
// baseline (speedup 1.0000x reference)
#include <cuda_runtime.h>
#include <cstdint>

#define BB 512
#define TT 1024
#define CC 256
#define LL 64
#define SS 129          // 2*LL+1
#define SPL 5           // states per lane (32*5 = 160 >= 129, padded)
#define DEPTH 8         // register prefetch depth (rows)
#define EPSF 1e-7f
#define NEGF (-1e30f)
#define LN2F 0.69314718055994530942f

__device__ __forceinline__ float ex2f(float x) {
    float y; asm("ex2.approx.ftz.f32 %0, %1;" : "=f"(y) : "f"(x)); return y;
}
__device__ __forceinline__ float lg2f(float x) {
    float y; asm("lg2.approx.ftz.f32 %0, %1;" : "=f"(y) : "f"(x)); return y;
}

// one CTC log-sum-exp step for a single state, log2 domain, emission folded in
__device__ __forceinline__ float lse3(float a1, float a2, float a3, float pe) {
    float m = fmaxf(fmaxf(a1, a2), a3);
    float s = ex2f(a1 - m) + ex2f(a2 - m) + ex2f(a3 - m);
    return m + lg2f(s * pe);
}

__global__ void __launch_bounds__(32)
ctc_warp_kernel(const int* __restrict__ y_true,
                const float* __restrict__ y_pred,
                float* __restrict__ out)
{
    __shared__ float buf[2][CC];

    const int b     = blockIdx.x;
    const int lane  = threadIdx.x;
    const int blank = CC - 1;

    const float* g = y_pred + (size_t)b * (size_t)(TT * CC) + lane * 8;

    // ---- static per-lane state info: class index + skip penalty for 5 states ----
    int   cls[SPL];
    float pen[SPL];     // 0 if skip (s-2 -> s) allowed, -1e30 otherwise
#pragma unroll
    for (int j = 0; j < SPL; j++) {
        int s = lane * SPL + j;
        int c = blank, c2 = blank;
        if (s < SS && (s & 1)) {
            c = y_true[b * LL + (s >> 1)];
            if (s >= 3) c2 = y_true[b * LL + (s >> 1) - 1];
        }
        cls[j] = c;
        pen[j] = (c != blank && c != c2) ? 0.0f : NEGF;
    }

    // ---- register prefetch pipeline: rows 0..7, 32B per lane, coalesced ----
    float4 pa[DEPTH], pb[DEPTH];
#pragma unroll
    for (int q = 0; q < DEPTH; q++) {
        pa[q] = *(const float4*)(g);
        pb[q] = *(const float4*)(g + 4);
        g += CC;
    }

    // ---- stage row 0, init alpha (log2 domain) ----
    *(float4*)&buf[0][lane * 8]     = pa[0];
    *(float4*)&buf[0][lane * 8 + 4] = pb[0];
    __syncwarp();

    float r0 = NEGF, r1 = NEGF, r2 = NEGF, r3 = NEGF, r4 = NEGF;
    if (lane == 0) {
        r0 = lg2f(buf[0][cls[0]] + EPSF);   // alpha[0] = log p(blank)
        r1 = lg2f(buf[0][cls[1]] + EPSF);   // alpha[1] = log p(label 0)
    }
    __syncwarp();

    // refill slot 0 with row 8
    pa[0] = *(const float4*)(g);
    pb[0] = *(const float4*)(g + 4);
    g += CC;

    for (int t0 = 1; t0 < TT; t0 += DEPTH) {
#pragma unroll
        for (int u = 0; u < DEPTH; u++) {
            const int t = t0 + u;          // t0 == 1 (mod 8)
            if (t >= TT) break;
            const int slot = (1 + u) & 7;  // == t & 7
            const int bsel = (1 + u) & 1;  // == t & 1

            // stage row t into SMEM double buffer
            *(float4*)&buf[bsel][lane * 8]     = pa[slot];
            *(float4*)&buf[bsel][lane * 8 + 4] = pb[slot];
            __syncwarp();

            // gather per-state emission probs (+eps), linear; log folded into lse3
            const float* st = &buf[bsel][0];
            float p0 = st[cls[0]] + EPSF;
            float p1 = st[cls[1]] + EPSF;
            float p2 = st[cls[2]] + EPSF;
            float p3 = st[cls[3]] + EPSF;
            float p4 = st[cls[4]] + EPSF;

            // prefetch row t+8 into the slot just consumed
            if (t + DEPTH < TT) {
                pa[slot] = *(const float4*)(g);
                pb[slot] = *(const float4*)(g + 4);
                g += CC;
            }

            // neighbor alphas from previous lane (old values)
            float u1 = __shfl_up_sync(0xffffffffu, r4, 1);  // alpha[s-1] for j=0
            float u2 = __shfl_up_sync(0xffffffffu, r3, 1);  // alpha[s-2] for j=0
            if (lane == 0) { u1 = NEGF; u2 = NEGF; }

            // CTC forward recursion, log2 domain
            float n0 = lse3(r0, u1, u2 + pen[0], p0);
            float n1 = lse3(r1, r0, u1 + pen[1], p1);
            float n2 = lse3(r2, r1, r0 + pen[2], p2);
            float n3 = lse3(r3, r2, r1 + pen[3], p3);
            float n4 = lse3(r4, r3, r2 + pen[4], p4);
            r0 = n0; r1 = n1; r2 = n2; r3 = n3; r4 = n4;
        }
    }

    // total = log2addexp(alpha[S-2], alpha[S-1]); S-1=128 -> lane25 r3, S-2=127 -> r2
    float tm  = fmaxf(r2, r3);
    float tot = tm + lg2f(ex2f(r2 - tm) + ex2f(r3 - tm));
    float v   = __shfl_sync(0xffffffffu, tot, (SS - 1) / SPL);
    if (lane == 0) out[b] = -LN2F * v;
}

extern "C" void kernel_launch(void* const* d_in, const int* in_sizes, int n_in,
                              void* d_out, int out_size)
{
    const int*   y_true = (const int*)d_in[0];
    const float* y_pred = (const float*)d_in[1];
    // defensive: swap by size if metadata order differs
    if (n_in >= 2 && in_sizes[0] > in_sizes[1]) {
        y_pred = (const float*)d_in[0];
        y_true = (const int*)d_in[1];
    }
    (void)out_size;
    ctc_warp_kernel<<<BB, 32>>>(y_true, y_pred, (float*)d_out);
}

// round 4
// speedup vs baseline: 1.1866x; 1.1866x over previous
#include <cuda_runtime.h>
#include <cstdint>

#define BB 512
#define TT 1024
#define CC 256
#define LL 64
#define SS 129          // 2*LL+1
#define SPL 5           // states per lane (32*5 = 160 >= 129, padded)
#define DEPTH 8         // register prefetch depth (rows)
#define EPSF 1e-7f
#define LN2F 0.69314718055994530942f

__global__ void __launch_bounds__(32)
ctc_warp_kernel(const int* __restrict__ y_true,
                const float* __restrict__ y_pred,
                float* __restrict__ out)
{
    __shared__ float buf[2][CC];

    const int b     = blockIdx.x;
    const int lane  = threadIdx.x;
    const int blank = CC - 1;

    const float* g = y_pred + (size_t)b * (size_t)(TT * CC) + lane * 8;

    // ---- static per-lane state info: class index + skip mask for 5 states ----
    int   cls[SPL];
    float skf[SPL];     // 1 if skip (s-2 -> s) allowed, 0 otherwise
#pragma unroll
    for (int j = 0; j < SPL; j++) {
        int s = lane * SPL + j;
        int c = blank, c2 = blank;
        if (s < SS && (s & 1)) {
            c = y_true[b * LL + (s >> 1)];
            if (s >= 3) c2 = y_true[b * LL + (s >> 1) - 1];
        }
        cls[j] = c;
        skf[j] = (c != blank && c != c2) ? 1.0f : 0.0f;
    }

    // ---- register prefetch pipeline: rows 0..7, 32B per lane, coalesced ----
    float4 pa[DEPTH], pb[DEPTH];
#pragma unroll
    for (int q = 0; q < DEPTH; q++) {
        pa[q] = *(const float4*)(g);
        pb[q] = *(const float4*)(g + 4);
        g += CC;
    }

    // ---- stage row 0, init alpha: block-floating-point, alpha = m * 2^E ----
    *(float4*)&buf[0][lane * 8]     = pa[0];
    *(float4*)&buf[0][lane * 8 + 4] = pb[0];
    __syncwarp();

    float m0 = 0.f, m1 = 0.f, m2 = 0.f, m3 = 0.f, m4 = 0.f;
    int   E  = 0;
    if (lane == 0) {
        m0 = buf[0][cls[0]] + EPSF;   // alpha[0] = p(blank)
        m1 = buf[0][cls[1]] + EPSF;   // alpha[1] = p(label 0)
    }
    __syncwarp();

    // refill slot 0 with row 8
    pa[0] = *(const float4*)(g);
    pb[0] = *(const float4*)(g + 4);
    g += CC;

    for (int t0 = 1; t0 < TT; t0 += DEPTH) {
#pragma unroll
        for (int u = 0; u < DEPTH; u++) {
            const int t = t0 + u;          // t0 == 1 (mod 8)
            if (t >= TT) break;
            const int slot = (1 + u) & 7;  // == t & 7
            const int bsel = (1 + u) & 1;  // == t & 1

            // stage row t into SMEM double buffer
            *(float4*)&buf[bsel][lane * 8]     = pa[slot];
            *(float4*)&buf[bsel][lane * 8 + 4] = pb[slot];
            __syncwarp();

            // gather per-state emission probs (+eps), linear domain
            const float* st = &buf[bsel][0];
            float p0 = st[cls[0]] + EPSF;
            float p1 = st[cls[1]] + EPSF;
            float p2 = st[cls[2]] + EPSF;
            float p3 = st[cls[3]] + EPSF;
            float p4 = st[cls[4]] + EPSF;

            // prefetch row t+8 into the slot just consumed
            if (t + DEPTH < TT) {
                pa[slot] = *(const float4*)(g);
                pb[slot] = *(const float4*)(g + 4);
                g += CC;
            }

            // neighbor mantissas/exponent from previous lane (old values)
            float nb4 = __shfl_up_sync(0xffffffffu, m4, 1);  // alpha[s-1] for j=0
            float nb3 = __shfl_up_sync(0xffffffffu, m3, 1);  // alpha[s-2] for j=0
            int   nbE = __shfl_up_sync(0xffffffffu, E,  1);
            if (lane == 0) { nb4 = 0.0f; nb3 = 0.0f; nbE = E; }

            // rescale self and neighbor into common exponent frame ec = max(E, nbE)
            int ec = (E > nbE) ? E : nbE;
            int dn = nbE - ec; if (dn < -126) dn = -126;   // <= 0
            int ds = E   - ec; if (ds < -126) ds = -126;   // <= 0
            float sn = __int_as_float((dn + 127) << 23);   // 2^dn
            float ss = __int_as_float((ds + 127) << 23);   // 2^ds

            float u1 = nb4 * sn;
            float u2 = nb3 * sn;
            float a0 = m0 * ss, a1 = m1 * ss, a2 = m2 * ss,
                  a3 = m3 * ss, a4 = m4 * ss;

            // CTC forward recursion (linear, frame 2^ec)
            float n0 = (a0 + u1 + skf[0] * u2) * p0;
            float n1 = (a1 + a0 + skf[1] * u1) * p1;
            float n2 = (a2 + a1 + skf[2] * a0) * p2;
            float n3 = (a3 + a2 + skf[3] * a1) * p3;
            float n4 = (a4 + a3 + skf[4] * a2) * p4;

            // renormalize lane block: bring max mantissa to [0.5, 1)
            float M = fmaxf(fmaxf(fmaxf(n0, n1), fmaxf(n2, n3)), n4);
            int eb = __float_as_int(M) >> 23;              // biased exponent of M (M >= 0)
            float rs = __int_as_float((254 - eb) << 23);   // 2^(127-eb)
            m0 = n0 * rs; m1 = n1 * rs; m2 = n2 * rs;
            m3 = n3 * rs; m4 = n4 * rs;
            // zero lane: adopt neighbor exponent so future inflow is scaled sanely
            E = (M > 0.0f) ? (ec + eb - 127) : nbE;
        }
    }

    // loss = -ln(alpha[S-2] + alpha[S-1]); S-1=128 -> lane25 m3, S-2=127 -> m2
    float tot = m2 + m3;                                   // mantissa sum, frame 2^E
    float lf  = (float)E + log2f(fmaxf(tot, 1e-37f));
    float v   = __shfl_sync(0xffffffffu, lf, (SS - 1) / SPL);
    if (lane == 0) out[b] = -LN2F * v;
}

extern "C" void kernel_launch(void* const* d_in, const int* in_sizes, int n_in,
                              void* d_out, int out_size)
{
    const int*   y_true = (const int*)d_in[0];
    const float* y_pred = (const float*)d_in[1];
    // defensive: swap by size if metadata order differs
    if (n_in >= 2 && in_sizes[0] > in_sizes[1]) {
        y_pred = (const float*)d_in[0];
        y_true = (const int*)d_in[1];
    }
    (void)out_size;
    ctc_warp_kernel<<<BB, 32>>>(y_true, y_pred, (float*)d_out);
}

// round 5
// speedup vs baseline: 3.0751x; 2.5914x over previous
#include <cuda_runtime.h>
#include <cstdint>

#define BB 512
#define TT 1024
#define CC 256
#define LL 64
#define SS 129          // 2*LL+1
#define SPL 5           // states per lane (32*5 = 160 >= 129, padded)
#define WROWS 8         // rows per memory window
#define NW (TT / WROWS) // 128 windows
#define EPSF 1e-7f
#define LN2F 0.69314718055994530942f
#define FULLM 0xffffffffu

__device__ __forceinline__ void cpa16(uint32_t dst, const float* src) {
    asm volatile("cp.async.cg.shared.global [%0], [%1], 16;" :: "r"(dst), "l"(src) : "memory");
}
__device__ __forceinline__ void cpcommit() {
    asm volatile("cp.async.commit_group;" ::: "memory");
}
__device__ __forceinline__ void cpwait1() {
    asm volatile("cp.async.wait_group 1;" ::: "memory");
}

__global__ void __launch_bounds__(32)
ctc_warp_kernel(const int* __restrict__ y_true,
                const float* __restrict__ y_pred,
                float* __restrict__ out)
{
    __shared__ float ring[2][WROWS][CC];   // 16 KB

    const int b     = blockIdx.x;
    const int lane  = threadIdx.x;
    const int blank = CC - 1;

    // ---- static per-lane state info ----
    int   cls[SPL];
    float skf[SPL];     // 1 if skip (s-2 -> s) allowed, 0 otherwise
#pragma unroll
    for (int j = 0; j < SPL; j++) {
        int s = lane * SPL + j;
        int c = blank, c2 = blank;
        if (s < SS && (s & 1)) {
            c = y_true[b * LL + (s >> 1)];
            if (s >= 3) c2 = y_true[b * LL + (s >> 1) - 1];
        }
        cls[j] = c;
        skf[j] = (c != blank && c != c2) ? 1.0f : 0.0f;
    }

    // ---- cp.async window pipeline ----
    const float* gsrc = y_pred + (size_t)b * (size_t)(TT * CC) + lane * 8;
    uint32_t sbase = (uint32_t)__cvta_generic_to_shared(&ring[0][0][0]);

    // prefill windows 0 and 1 (one commit group per window)
#pragma unroll
    for (int w0 = 0; w0 < 2; w0++) {
#pragma unroll
        for (int r = 0; r < WROWS; r++) {
            uint32_t dst = sbase + (uint32_t)(((w0 & 1) * WROWS + r) * CC + lane * 8) * 4u;
            cpa16(dst, gsrc);
            cpa16(dst + 16, gsrc + 4);
            gsrc += CC;
        }
        cpcommit();
    }

    // block-floating-point state: alpha = m * 2^E (per-lane frame)
    float m0 = 0.f, m1 = 0.f, m2 = 0.f, m3 = 0.f, m4 = 0.f;
    int   E  = 0;

    for (int w = 0; w < NW; ++w) {
        cpwait1();          // window w landed
        __syncwarp();       // publish all lanes' copies

        // bulk-gather emission probs for the whole window (off the chain)
        float P[WROWS][SPL];
        const float (*rb)[CC] = ring[w & 1];
#pragma unroll
        for (int r = 0; r < WROWS; r++)
#pragma unroll
            for (int j = 0; j < SPL; j++)
                P[r][j] = rb[r][cls[j]] + EPSF;
        __syncwarp();       // everyone done reading before overwrite

        // prefetch window w+2 into the buffer just freed
        if (w + 2 < NW) {
#pragma unroll
            for (int r = 0; r < WROWS; r++) {
                uint32_t dst = sbase + (uint32_t)(((w & 1) * WROWS + r) * CC + lane * 8) * 4u;
                cpa16(dst, gsrc);
                cpa16(dst + 16, gsrc + 4);
                gsrc += CC;
            }
        }
        cpcommit();         // unconditional: keeps group accounting uniform

        if (w == 0 && lane == 0) {
            m0 = P[0][0];   // alpha[0] = p(blank) at t=0
            m1 = P[0][1];   // alpha[1] = p(label 0)
        }

#pragma unroll
        for (int half = 0; half < 2; ++half) {
            // frame setup once per 4 steps
            int nbE = __shfl_up_sync(FULLM, E, 1);
            if (lane == 0) nbE = E;
            int d = nbE - E;
            d = d < -96 ? -96 : (d > 96 ? 96 : d);
            float sn = __int_as_float((d + 127) << 23);   // 2^(nbE-E), clamped

#pragma unroll
            for (int q = 0; q < 4; ++q) {
                const int u = half * 4 + q;
                if (w == 0 && u == 0) continue;           // t=0 consumed by init

                float nb4 = __shfl_up_sync(FULLM, m4, 1); // alpha[s-1] for j=0
                float nb3 = __shfl_up_sync(FULLM, m3, 1); // alpha[s-2] for j=0
                float u1 = lane ? nb4 * sn : 0.0f;
                float u2 = lane ? nb3 * sn : 0.0f;

                float n0 = (m0 + u1 + skf[0] * u2) * P[u][0];
                float n1 = (m1 + m0 + skf[1] * u1) * P[u][1];
                float n2 = (m2 + m1 + skf[2] * m0) * P[u][2];
                float n3 = (m3 + m2 + skf[3] * m1) * P[u][3];
                float n4 = (m4 + m3 + skf[4] * m2) * P[u][4];
                m0 = n0; m1 = n1; m2 = n2; m3 = n3; m4 = n4;
            }

            // renormalize once per 4 steps: lane max mantissa -> [1,2)
            float M = fmaxf(fmaxf(fmaxf(m0, m1), fmaxf(m2, m3)), m4);
            int eb = __float_as_int(M) >> 23;             // biased exponent (M >= 0)
            float rs = __int_as_float((254 - eb) << 23);  // 2^(127-eb)
            m0 *= rs; m1 *= rs; m2 *= rs; m3 *= rs; m4 *= rs;
            // dead lane adopts neighbor's exponent so future inflow scales sanely
            E = (M > 0.0f) ? (E + eb - 127) : nbE;
        }
    }

    // loss = -ln(alpha[S-2] + alpha[S-1]); S-1=128 -> lane25 m3, S-2=127 -> m2
    float tot = m2 + m3;                                  // frame 2^E
    float lf  = (float)E + log2f(fmaxf(tot, 1e-45f));
    float v   = __shfl_sync(FULLM, lf, (SS - 1) / SPL);
    if (lane == 0) out[b] = -LN2F * v;
}

extern "C" void kernel_launch(void* const* d_in, const int* in_sizes, int n_in,
                              void* d_out, int out_size)
{
    const int*   y_true = (const int*)d_in[0];
    const float* y_pred = (const float*)d_in[1];
    // defensive: swap by size if metadata order differs
    if (n_in >= 2 && in_sizes[0] > in_sizes[1]) {
        y_pred = (const float*)d_in[0];
        y_true = (const int*)d_in[1];
    }
    (void)out_size;
    ctc_warp_kernel<<<BB, 32>>>(y_true, y_pred, (float*)d_out);
}

// round 6
// speedup vs baseline: 3.1145x; 1.0128x over previous
#include <cuda_runtime.h>
#include <cstdint>

#define BB 512
#define TT 1024
#define CC 256
#define LL 64
#define SS 129          // 2*LL+1
#define SPL 5           // states per lane (32*5 = 160 >= 129, padded)
#define WROWS 8         // rows per memory window
#define NW (TT / WROWS) // 128 windows
#define RING 6          // ring depth in windows (6 * 8 rows * 1KB = 48KB)
#define PREF 5          // prefetch distance (windows)
#define EPSF 1e-7f
#define LN2F 0.69314718055994530942f
#define FULLM 0xffffffffu

__device__ __forceinline__ void cpa16(uint32_t dst, const float* src) {
    asm volatile("cp.async.cg.shared.global [%0], [%1], 16;" :: "r"(dst), "l"(src) : "memory");
}
__device__ __forceinline__ void cpcommit() {
    asm volatile("cp.async.commit_group;" ::: "memory");
}
__device__ __forceinline__ void cpwait4() {
    asm volatile("cp.async.wait_group 4;" ::: "memory");
}

__global__ void __launch_bounds__(32)
ctc_warp_kernel(const int* __restrict__ y_true,
                const float* __restrict__ y_pred,
                float* __restrict__ out)
{
    __shared__ float ring[RING][WROWS][CC];   // 48 KB

    const int b     = blockIdx.x;
    const int lane  = threadIdx.x;
    const int blank = CC - 1;

    // ---- static per-lane state info ----
    int   cls[SPL];
    float skf[SPL];     // 1 if skip (s-2 -> s) allowed, 0 otherwise
#pragma unroll
    for (int j = 0; j < SPL; j++) {
        int s = lane * SPL + j;
        int c = blank, c2 = blank;
        if (s < SS && (s & 1)) {
            c = y_true[b * LL + (s >> 1)];
            if (s >= 3) c2 = y_true[b * LL + (s >> 1) - 1];
        }
        cls[j] = c;
        skf[j] = (c != blank && c != c2) ? 1.0f : 0.0f;
    }

    // ---- cp.async window pipeline: prefill windows 0..PREF-1 ----
    const float* gsrc = y_pred + (size_t)b * (size_t)(TT * CC) + lane * 8;
    uint32_t sbase = (uint32_t)__cvta_generic_to_shared(&ring[0][0][0]);

#pragma unroll
    for (int w0 = 0; w0 < PREF; w0++) {
#pragma unroll
        for (int r = 0; r < WROWS; r++) {
            uint32_t dst = sbase + (uint32_t)((w0 * WROWS + r) * CC + lane * 8) * 4u;
            cpa16(dst, gsrc);
            cpa16(dst + 16, gsrc + 4);
            gsrc += CC;
        }
        cpcommit();
    }

    // block-floating-point state: alpha = m * 2^E (per-lane frame)
    float m0 = 0.f, m1 = 0.f, m2 = 0.f, m3 = 0.f, m4 = 0.f;
    int   E  = 0;

    int slot = 0;                    // w % RING
    int pslot = PREF;                // (w + PREF) % RING

    for (int w = 0; w < NW; ++w) {
        cpwait4();          // window w landed (pending was 5; retires oldest)
        __syncwarp();       // publish all lanes' copies

        // bulk-gather emission probs for the whole window (off the chain)
        float P[WROWS][SPL];
        const float (*rb)[CC] = ring[slot];
#pragma unroll
        for (int r = 0; r < WROWS; r++)
#pragma unroll
            for (int j = 0; j < SPL; j++)
                P[r][j] = rb[r][cls[j]] + EPSF;
        __syncwarp();       // everyone done reading before any slot reuse

        // prefetch window w+PREF into slot (w+PREF)%RING (last read at iter w-1)
        if (w + PREF < NW) {
#pragma unroll
            for (int r = 0; r < WROWS; r++) {
                uint32_t dst = sbase + (uint32_t)((pslot * WROWS + r) * CC + lane * 8) * 4u;
                cpa16(dst, gsrc);
                cpa16(dst + 16, gsrc + 4);
                gsrc += CC;
            }
        }
        cpcommit();         // unconditional: keeps group accounting uniform

        slot  = (slot  == RING - 1) ? 0 : slot + 1;
        pslot = (pslot == RING - 1) ? 0 : pslot + 1;

        if (w == 0 && lane == 0) {
            m0 = P[0][0];   // alpha[0] = p(blank) at t=0
            m1 = P[0][1];   // alpha[1] = p(label 0)
        }

#pragma unroll
        for (int half = 0; half < 2; ++half) {
            // frame setup once per 4 steps
            int nbE = __shfl_up_sync(FULLM, E, 1);
            if (lane == 0) nbE = E;
            int d = nbE - E;
            d = d < -96 ? -96 : (d > 96 ? 96 : d);
            float sn = __int_as_float((d + 127) << 23);   // 2^(nbE-E), clamped

#pragma unroll
            for (int q = 0; q < 4; ++q) {
                const int u = half * 4 + q;
                if (w == 0 && u == 0) continue;           // t=0 consumed by init

                float nb4 = __shfl_up_sync(FULLM, m4, 1); // alpha[s-1] for j=0
                float nb3 = __shfl_up_sync(FULLM, m3, 1); // alpha[s-2] for j=0
                float u1 = lane ? nb4 * sn : 0.0f;
                float u2 = lane ? nb3 * sn : 0.0f;

                float n0 = (m0 + u1 + skf[0] * u2) * P[u][0];
                float n1 = (m1 + m0 + skf[1] * u1) * P[u][1];
                float n2 = (m2 + m1 + skf[2] * m0) * P[u][2];
                float n3 = (m3 + m2 + skf[3] * m1) * P[u][3];
                float n4 = (m4 + m3 + skf[4] * m2) * P[u][4];
                m0 = n0; m1 = n1; m2 = n2; m3 = n3; m4 = n4;
            }

            // renormalize once per 4 steps: lane max mantissa -> [1,2)
            float M = fmaxf(fmaxf(fmaxf(m0, m1), fmaxf(m2, m3)), m4);
            int eb = __float_as_int(M) >> 23;             // biased exponent (M >= 0)
            float rs = __int_as_float((254 - eb) << 23);  // 2^(127-eb)
            m0 *= rs; m1 *= rs; m2 *= rs; m3 *= rs; m4 *= rs;
            // dead lane adopts neighbor's exponent so future inflow scales sanely
            E = (M > 0.0f) ? (E + eb - 127) : nbE;
        }
    }

    // loss = -ln(alpha[S-2] + alpha[S-1]); S-1=128 -> lane25 m3, S-2=127 -> m2
    float tot = m2 + m3;                                  // frame 2^E
    float lf  = (float)E + log2f(fmaxf(tot, 1e-45f));
    float v   = __shfl_sync(FULLM, lf, (SS - 1) / SPL);
    if (lane == 0) out[b] = -LN2F * v;
}

extern "C" void kernel_launch(void* const* d_in, const int* in_sizes, int n_in,
                              void* d_out, int out_size)
{
    const int*   y_true = (const int*)d_in[0];
    const float* y_pred = (const float*)d_in[1];
    // defensive: swap by size if metadata order differs
    if (n_in >= 2 && in_sizes[0] > in_sizes[1]) {
        y_pred = (const float*)d_in[0];
        y_true = (const int*)d_in[1];
    }
    (void)out_size;
    ctc_warp_kernel<<<BB, 32>>>(y_true, y_pred, (float*)d_out);
}